// round 1
// baseline (speedup 1.0000x reference)
#include <cuda_runtime.h>
#include <cstdint>
#include <cstdio>

#define BB   8
#define SS   128
#define DD   300
#define EE   50
#define DEPC 50
#define RROWS 8
#define NTHR 320

// ---------------- scratch (static device globals; no allocation) ----------------
__device__ float g_M [BB * SS * SS];     // mean-over-experts adjacency, 512 KB
__device__ float g_Pa[BB * SS * DEPC];   // node @ Wa^T
__device__ float g_Pb[BB * SS * DEPC];   // node @ Wb^T

using ull = unsigned long long;

// ---------------- f32x2 packed-math helpers (Blackwell sm_100a+) ----------------
__device__ __forceinline__ ull pk2(float x, float y) {
    ull r; asm("mov.b64 %0, {%1,%2};" : "=l"(r) : "f"(x), "f"(y)); return r;
}
__device__ __forceinline__ ull f2fma(ull a, ull b, ull c) {
    ull d; asm("fma.rn.f32x2 %0, %1, %2, %3;" : "=l"(d) : "l"(a), "l"(b), "l"(c)); return d;
}
__device__ __forceinline__ void upk2(ull v, float& x, float& y) {
    asm("mov.b64 {%0,%1}, %2;" : "=f"(x), "=f"(y) : "l"(v));
}

// =======================================================================
// Kernel A: M[b,s,t] = (1/E) * ( sum_e wps[b,s,t,e] + sum_e sl[b,e,s,t] )
// Pure HBM reduction: 52 MB read, 0.5 MB write.
// =======================================================================
__global__ void k_reduceM(const float* __restrict__ wps, const float* __restrict__ sl) {
    int idx = blockIdx.x * blockDim.x + threadIdx.x;   // over B*S*S = 131072
    if (idx >= BB * SS * SS) return;
    int b  = idx >> 14;          // / (S*S)
    int st = idx & 16383;

    // wps: last-dim-contiguous 50 floats per thread (8B aligned -> float2)
    const float2* wp2 = reinterpret_cast<const float2*>(wps + (size_t)idx * EE);
    float s = 0.f;
#pragma unroll
    for (int i = 0; i < EE / 2; i++) { float2 v = wp2[i]; s += v.x + v.y; }

    // self_loop: stride S*S over e, coalesced across threads
    const float* sp = sl + (size_t)b * EE * SS * SS + st;
#pragma unroll
    for (int e = 0; e < EE; e++) s += sp[e * SS * SS];

    g_M[idx] = s * (1.0f / EE);
}

// =======================================================================
// Kernel B: per (b, 8-row group):
//   Ax = M_rows @ X_b            (X_b staged in smem)
//   g  = Ax @ W^T + b ; LayerNorm(ddof=1) ; node = relu
//   pa = node @ Wa^T ; pb = node @ Wb^T
// Row pairs packed into f32x2 so every smem operand read is a broadcast.
// =======================================================================
#define SMEM_FLOATS 45520
#define SMEM_BYTES  (SMEM_FLOATS * 4)

#define AXU(d, rp) (*reinterpret_cast<const ull*>(&AxP[(d) * 5 + (rp)]))
#define NSU(d, rp) (*reinterpret_cast<const ull*>(&NsP[(d) * 5 + (rp)]))

__global__ __launch_bounds__(NTHR, 1) void k_node(
    const float* __restrict__ x,   const float* __restrict__ Ww,
    const float* __restrict__ Wb,  const float* __restrict__ lna,
    const float* __restrict__ lnb, const float* __restrict__ W1w,
    float* __restrict__ node_out)
{
    extern __shared__ float sm[];
    float*  Xs    = sm;                                   // [0, 38400)   X_b [t][d]
    float2* MsP   = reinterpret_cast<float2*>(sm + 38400); // 512 f2: [t*4+rp] = (M[2rp][t], M[2rp+1][t])
    float2* AxP   = reinterpret_cast<float2*>(sm + 39424); // 1500 f2: [d*5+rp]
    float2* NsP   = reinterpret_cast<float2*>(sm + 42424); // 1500 f2: [d*5+rp]
    float*  red   = sm + 45424;                            // 80
    float*  means = sm + 45504;                            // 8
    float*  invd  = sm + 45512;                            // 8

    const int tid = threadIdx.x;
    const int b   = blockIdx.x >> 4;            // / 16 groups
    const int s0  = (blockIdx.x & 15) * RROWS;

    // ---- stage X_b (128x300 f32 = 150 KB) ----
    const float4* xb4 = reinterpret_cast<const float4*>(x + (size_t)b * SS * DD);
    float4* Xs4 = reinterpret_cast<float4*>(Xs);
    for (int i = tid; i < SS * DD / 4; i += NTHR) Xs4[i] = xb4[i];

    // ---- stage M rows, packed by row-pair ----
    const float* Mb = g_M + (b * SS + s0) * SS;
    for (int i = tid; i < SS * (RROWS / 2); i += NTHR) {
        int t = i >> 2, rp = i & 3;
        MsP[i] = make_float2(Mb[(2 * rp) * SS + t], Mb[(2 * rp + 1) * SS + t]);
    }
    __syncthreads();

    // ---- Phase 1: Ax[r][d] = sum_t M[r][t] * X[t][d] (thread owns d) ----
    if (tid < DD) {
        ull acc[4] = {0, 0, 0, 0};
#pragma unroll 4
        for (int t = 0; t < SS; t++) {
            float xv = Xs[t * DD + tid];
            ull x2 = pk2(xv, xv);
#pragma unroll
            for (int rp = 0; rp < 4; rp++)
                acc[rp] = f2fma(*reinterpret_cast<const ull*>(&MsP[t * 4 + rp]), x2, acc[rp]);
        }
#pragma unroll
        for (int rp = 0; rp < 4; rp++)
            *reinterpret_cast<ull*>(&AxP[tid * 5 + rp]) = acc[rp];
    }
    __syncthreads();

    // ---- Phase 2: g[r][j] = sum_d Ax[r][d] * W[j][d] + b[j] (thread owns j) ----
    float gv[RROWS];
#pragma unroll
    for (int r = 0; r < RROWS; r++) gv[r] = 0.f;

    if (tid < DD) {
        const float4* w4 = reinterpret_cast<const float4*>(Ww + tid * DD);
        ull acc[4] = {0, 0, 0, 0};
        for (int d4 = 0; d4 < DD / 4; d4++) {
            float4 wq = w4[d4];
            int d = d4 * 4;
            ull w2;
            w2 = pk2(wq.x, wq.x);
#pragma unroll
            for (int rp = 0; rp < 4; rp++) acc[rp] = f2fma(w2, AXU(d + 0, rp), acc[rp]);
            w2 = pk2(wq.y, wq.y);
#pragma unroll
            for (int rp = 0; rp < 4; rp++) acc[rp] = f2fma(w2, AXU(d + 1, rp), acc[rp]);
            w2 = pk2(wq.z, wq.z);
#pragma unroll
            for (int rp = 0; rp < 4; rp++) acc[rp] = f2fma(w2, AXU(d + 2, rp), acc[rp]);
            w2 = pk2(wq.w, wq.w);
#pragma unroll
            for (int rp = 0; rp < 4; rp++) acc[rp] = f2fma(w2, AXU(d + 3, rp), acc[rp]);
        }
        float bj = Wb[tid];
#pragma unroll
        for (int rp = 0; rp < 4; rp++) upk2(acc[rp], gv[2 * rp], gv[2 * rp + 1]);
#pragma unroll
        for (int r = 0; r < RROWS; r++) gv[r] += bj;
    }

    // ---- Phase 3: LayerNorm (two-pass, ddof=1) + relu ----
    const int lane = tid & 31, warp = tid >> 5;
    {
        float s[RROWS];
#pragma unroll
        for (int r = 0; r < RROWS; r++) s[r] = gv[r];
#pragma unroll
        for (int off = 16; off; off >>= 1)
#pragma unroll
            for (int r = 0; r < RROWS; r++) s[r] += __shfl_down_sync(0xffffffffu, s[r], off);
        if (lane == 0)
#pragma unroll
            for (int r = 0; r < RROWS; r++) red[warp * RROWS + r] = s[r];
    }
    __syncthreads();
    if (tid < RROWS) {
        float s = 0.f;
#pragma unroll
        for (int w = 0; w < NTHR / 32; w++) s += red[w * RROWS + tid];
        means[tid] = s * (1.0f / DD);
    }
    __syncthreads();
    {
        float s[RROWS];
#pragma unroll
        for (int r = 0; r < RROWS; r++) {
            float dv = (tid < DD) ? (gv[r] - means[r]) : 0.f;
            s[r] = dv * dv;
        }
#pragma unroll
        for (int off = 16; off; off >>= 1)
#pragma unroll
            for (int r = 0; r < RROWS; r++) s[r] += __shfl_down_sync(0xffffffffu, s[r], off);
        if (lane == 0)
#pragma unroll
            for (int r = 0; r < RROWS; r++) red[warp * RROWS + r] = s[r];
    }
    __syncthreads();
    if (tid < RROWS) {
        float s = 0.f;
#pragma unroll
        for (int w = 0; w < NTHR / 32; w++) s += red[w * RROWS + tid];
        float stdv = sqrtf(s * (1.0f / (DD - 1)));   // ddof = 1
        invd[tid] = 1.0f / (stdv + 1e-6f);
    }
    __syncthreads();

    if (tid < DD) {
        float a = lna[tid], bb2 = lnb[tid];
        float nv[RROWS];
#pragma unroll
        for (int r = 0; r < RROWS; r++) {
            float v = a * (gv[r] - means[r]) * invd[r] + bb2;
            nv[r] = v > 0.f ? v : 0.f;
            node_out[(b * SS + s0 + r) * DD + tid] = nv[r];
        }
#pragma unroll
        for (int rp = 0; rp < 4; rp++)
            NsP[tid * 5 + rp] = make_float2(nv[2 * rp], nv[2 * rp + 1]);
    }
    __syncthreads();

    // ---- Phase 4: pa/pb (thread owns output column; 100 active threads) ----
    if (tid < 2 * DEPC) {
        int e = tid % DEPC;
        int half = tid / DEPC;     // 0 = pa (W1[:, :D]), 1 = pb (W1[:, D:])
        const float4* w4 = reinterpret_cast<const float4*>(W1w + e * (2 * DD) + half * DD);
        ull acc[4] = {0, 0, 0, 0};
        for (int d4 = 0; d4 < DD / 4; d4++) {
            float4 wq = w4[d4];
            int d = d4 * 4;
            ull w2;
            w2 = pk2(wq.x, wq.x);
#pragma unroll
            for (int rp = 0; rp < 4; rp++) acc[rp] = f2fma(w2, NSU(d + 0, rp), acc[rp]);
            w2 = pk2(wq.y, wq.y);
#pragma unroll
            for (int rp = 0; rp < 4; rp++) acc[rp] = f2fma(w2, NSU(d + 1, rp), acc[rp]);
            w2 = pk2(wq.z, wq.z);
#pragma unroll
            for (int rp = 0; rp < 4; rp++) acc[rp] = f2fma(w2, NSU(d + 2, rp), acc[rp]);
            w2 = pk2(wq.w, wq.w);
#pragma unroll
            for (int rp = 0; rp < 4; rp++) acc[rp] = f2fma(w2, NSU(d + 3, rp), acc[rp]);
        }
        float pv[RROWS];
#pragma unroll
        for (int rp = 0; rp < 4; rp++) upk2(acc[rp], pv[2 * rp], pv[2 * rp + 1]);
        float* dst = (half == 0 ? g_Pa : g_Pb) + (b * SS + s0) * DEPC + e;
#pragma unroll
        for (int r = 0; r < RROWS; r++) dst[r * DEPC] = pv[r];
    }
}

// =======================================================================
// Kernel C: edge[b,i,j,e] = pa[b,j,e] + pb[b,i,e] + W1_b[e]
// 26 MB streaming write; float2-vectorized (pairs never straddle e=50).
// =======================================================================
__global__ void k_edge(const float* __restrict__ W1b, float* __restrict__ edge) {
    __shared__ float2 pb2[DEPC / 2];
    const int bi  = blockIdx.x;        // b*S + i
    const int b   = bi >> 7;
    const int tid = threadIdx.x;

    if (tid < DEPC / 2) {
        int e = tid * 2;
        pb2[tid] = make_float2(g_Pb[bi * DEPC + e]     + W1b[e],
                               g_Pb[bi * DEPC + e + 1] + W1b[e + 1]);
    }
    __syncthreads();

    const float2* pa2  = reinterpret_cast<const float2*>(g_Pa + b * SS * DEPC);
    float2*       out2 = reinterpret_cast<float2*>(edge + (size_t)bi * SS * DEPC);
    for (int i2 = tid; i2 < SS * DEPC / 2; i2 += blockDim.x) {
        float2 a = pa2[i2];
        float2 p = pb2[i2 % (DEPC / 2)];
        out2[i2] = make_float2(a.x + p.x, a.y + p.y);
    }
}

// =======================================================================
extern "C" void kernel_launch(void* const* d_in, const int* in_sizes, int n_in,
                              void* d_out, int out_size) {
    const float* wps = (const float*)d_in[0];
    /* d_in[1] = weight_adj (int64) — unused by the reference computation */
    const float* x   = (const float*)d_in[2];
    const float* sl  = (const float*)d_in[3];
    const float* Ww  = (const float*)d_in[4];
    const float* Wb  = (const float*)d_in[5];
    const float* lna = (const float*)d_in[6];
    const float* lnb = (const float*)d_in[7];
    const float* W1w = (const float*)d_in[8];
    const float* W1b = (const float*)d_in[9];

    float* out  = (float*)d_out;
    float* node = out;                       // B*S*D = 307200 floats
    float* edge = out + BB * SS * DD;        // B*S*S*DEP = 6553600 floats

    cudaFuncSetAttribute((const void*)k_node,
                         cudaFuncAttributeMaxDynamicSharedMemorySize, SMEM_BYTES);

    k_reduceM<<<(BB * SS * SS + 255) / 256, 256>>>(wps, sl);
    k_node<<<BB * (SS / RROWS), NTHR, SMEM_BYTES>>>(x, Ww, Wb, lna, lnb, W1w, node);
    k_edge<<<BB * SS, 256>>>(W1b, edge);
}

// round 3
// speedup vs baseline: 1.0798x; 1.0798x over previous
#include <cuda_runtime.h>
#include <cstdint>
#include <cstdio>

#define BB   8
#define SS   128
#define DD   300
#define EE   50
#define DEPC 50
#define RROWS 8
#define NTHR 320

// ---------------- scratch (static device globals; no allocation) ----------------
__device__ float g_Pa[BB * SS * DEPC];   // node @ Wa^T
__device__ float g_Pb[BB * SS * DEPC];   // node @ Wb^T

using ull = unsigned long long;

// ---------------- f32x2 packed-math helpers (Blackwell sm_100a+) ----------------
__device__ __forceinline__ ull pk2(float x, float y) {
    ull r; asm("mov.b64 %0, {%1,%2};" : "=l"(r) : "f"(x), "f"(y)); return r;
}
__device__ __forceinline__ ull f2fma(ull a, ull b, ull c) {
    ull d; asm("fma.rn.f32x2 %0, %1, %2, %3;" : "=l"(d) : "l"(a), "l"(b), "l"(c)); return d;
}
__device__ __forceinline__ void upk2(ull v, float& x, float& y) {
    asm("mov.b64 {%0,%1}, %2;" : "=f"(x), "=f"(y) : "l"(v));
}

// =======================================================================
// Fused kernel: per (b, 8-row group):
//   M_rows = (1/E)(sum_e wps[b,s,:,e] + sum_e sl[b,e,s,:])   [in smem]
//   Ax = M_rows @ X_b            (X_b staged in smem)
//   g  = Ax @ W^T + b ; LayerNorm(ddof=1) ; node = relu
//   pa = node @ Wa^T ; pb = node @ Wb^T  (3-way D-split across threads)
// Row pairs packed into f32x2 so every smem operand read is a broadcast.
// =======================================================================
#define SMEM_FLOATS 45520
#define SMEM_BYTES  (SMEM_FLOATS * 4)

#define AXU(d, rp) (*reinterpret_cast<const ull*>(&AxP[(d) * 5 + (rp)]))
#define NSU(d, rp) (*reinterpret_cast<const ull*>(&NsP[(d) * 5 + (rp)]))

__global__ __launch_bounds__(NTHR, 1) void k_fused(
    const float* __restrict__ wps, const float* __restrict__ sl,
    const float* __restrict__ x,   const float* __restrict__ Ww,
    const float* __restrict__ Wb,  const float* __restrict__ lna,
    const float* __restrict__ lnb, const float* __restrict__ W1w,
    float* __restrict__ node_out)
{
    extern __shared__ float sm[];
    float*  Xs    = sm;                                    // [0, 38400)   X_b [t][d]
    float*  MsPf  = sm + 38400;                            // 1024: packed M row-pairs
    float2* MsP   = reinterpret_cast<float2*>(MsPf);       // [t*4+rp] = (M[2rp][t], M[2rp+1][t])
    float2* AxP   = reinterpret_cast<float2*>(sm + 39424); // 1500 f2: [d*5+rp]  (reused for ph4 partials)
    float2* NsP   = reinterpret_cast<float2*>(sm + 42424); // 1500 f2: [d*5+rp]
    float*  red   = sm + 45424;                            // 80
    float*  means = sm + 45504;                            // 8
    float*  invd  = sm + 45512;                            // 8

    const int tid = threadIdx.x;
    const int b   = blockIdx.x >> 4;            // / 16 groups
    const int s0  = (blockIdx.x & 15) * RROWS;

    // ---- Phase 0a: stage X_b (128x300 f32 = 150 KB) ----
    const float4* xb4 = reinterpret_cast<const float4*>(x + (size_t)b * SS * DD);
    float4* Xs4 = reinterpret_cast<float4*>(Xs);
#pragma unroll
    for (int i = tid; i < SS * DD / 4; i += NTHR) Xs4[i] = xb4[i];

    // ---- Phase 0b: compute this block's 8 M-rows directly into smem ----
    // entry k -> (r, t); each needs sum_e wps[b,s0+r,t,e] + sum_e sl[b,e,s0+r,t]
    for (int k = tid; k < RROWS * SS; k += NTHR) {
        int r = k >> 7, t = k & 127;
        const float2* wp2 = reinterpret_cast<const float2*>(
            wps + ((size_t)((b * SS + s0 + r) * SS) + t) * EE);
        float s = 0.f;
#pragma unroll
        for (int i = 0; i < EE / 2; i++) { float2 v = wp2[i]; s += v.x + v.y; }
        const float* sp = sl + (size_t)b * EE * SS * SS + (s0 + r) * SS + t;
#pragma unroll
        for (int e = 0; e < EE; e++) s += sp[e * SS * SS];
        MsPf[(t * 4 + (r >> 1)) * 2 + (r & 1)] = s * (1.0f / EE);
    }
    __syncthreads();

    // ---- Phase 1: Ax[r][d] = sum_t M[r][t] * X[t][d] (thread owns d) ----
    if (tid < DD) {
        ull acc[4] = {0, 0, 0, 0};
#pragma unroll 4
        for (int t = 0; t < SS; t++) {
            float xv = Xs[t * DD + tid];
            ull x2 = pk2(xv, xv);
#pragma unroll
            for (int rp = 0; rp < 4; rp++)
                acc[rp] = f2fma(*reinterpret_cast<const ull*>(&MsP[t * 4 + rp]), x2, acc[rp]);
        }
#pragma unroll
        for (int rp = 0; rp < 4; rp++)
            *reinterpret_cast<ull*>(&AxP[tid * 5 + rp]) = acc[rp];
    }
    __syncthreads();

    // ---- Phase 2: g[r][j] = sum_d Ax[r][d] * W[j][d] + b[j] (thread owns j) ----
    float gv[RROWS];
#pragma unroll
    for (int r = 0; r < RROWS; r++) gv[r] = 0.f;

    if (tid < DD) {
        const float4* w4 = reinterpret_cast<const float4*>(Ww + tid * DD);
        ull acc[4] = {0, 0, 0, 0};
        for (int d4 = 0; d4 < DD / 4; d4++) {
            float4 wq = w4[d4];
            int d = d4 * 4;
            ull w2;
            w2 = pk2(wq.x, wq.x);
#pragma unroll
            for (int rp = 0; rp < 4; rp++) acc[rp] = f2fma(w2, AXU(d + 0, rp), acc[rp]);
            w2 = pk2(wq.y, wq.y);
#pragma unroll
            for (int rp = 0; rp < 4; rp++) acc[rp] = f2fma(w2, AXU(d + 1, rp), acc[rp]);
            w2 = pk2(wq.z, wq.z);
#pragma unroll
            for (int rp = 0; rp < 4; rp++) acc[rp] = f2fma(w2, AXU(d + 2, rp), acc[rp]);
            w2 = pk2(wq.w, wq.w);
#pragma unroll
            for (int rp = 0; rp < 4; rp++) acc[rp] = f2fma(w2, AXU(d + 3, rp), acc[rp]);
        }
        float bj = Wb[tid];
#pragma unroll
        for (int rp = 0; rp < 4; rp++) upk2(acc[rp], gv[2 * rp], gv[2 * rp + 1]);
#pragma unroll
        for (int r = 0; r < RROWS; r++) gv[r] += bj;
    }

    // ---- Phase 3: LayerNorm (two-pass, ddof=1) + relu ----
    const int lane = tid & 31, warp = tid >> 5;
    {
        float s[RROWS];
#pragma unroll
        for (int r = 0; r < RROWS; r++) s[r] = gv[r];
#pragma unroll
        for (int off = 16; off; off >>= 1)
#pragma unroll
            for (int r = 0; r < RROWS; r++) s[r] += __shfl_down_sync(0xffffffffu, s[r], off);
        if (lane == 0)
#pragma unroll
            for (int r = 0; r < RROWS; r++) red[warp * RROWS + r] = s[r];
    }
    __syncthreads();
    if (tid < RROWS) {
        float s = 0.f;
#pragma unroll
        for (int w = 0; w < NTHR / 32; w++) s += red[w * RROWS + tid];
        means[tid] = s * (1.0f / DD);
    }
    __syncthreads();
    {
        float s[RROWS];
#pragma unroll
        for (int r = 0; r < RROWS; r++) {
            float dv = (tid < DD) ? (gv[r] - means[r]) : 0.f;
            s[r] = dv * dv;
        }
#pragma unroll
        for (int off = 16; off; off >>= 1)
#pragma unroll
            for (int r = 0; r < RROWS; r++) s[r] += __shfl_down_sync(0xffffffffu, s[r], off);
        if (lane == 0)
#pragma unroll
            for (int r = 0; r < RROWS; r++) red[warp * RROWS + r] = s[r];
    }
    __syncthreads();
    if (tid < RROWS) {
        float s = 0.f;
#pragma unroll
        for (int w = 0; w < NTHR / 32; w++) s += red[w * RROWS + tid];
        float stdv = sqrtf(s * (1.0f / (DD - 1)));   // ddof = 1
        invd[tid] = 1.0f / (stdv + 1e-6f);
    }
    __syncthreads();

    if (tid < DD) {
        float a = lna[tid], bb2 = lnb[tid];
        float nv[RROWS];
#pragma unroll
        for (int r = 0; r < RROWS; r++) {
            float v = a * (gv[r] - means[r]) * invd[r] + bb2;
            nv[r] = v > 0.f ? v : 0.f;
            node_out[(b * SS + s0 + r) * DD + tid] = nv[r];
        }
#pragma unroll
        for (int rp = 0; rp < 4; rp++)
            NsP[tid * 5 + rp] = make_float2(nv[2 * rp], nv[2 * rp + 1]);
    }
    __syncthreads();

    // ---- Phase 4: pa/pb, 3-way D-split (300 active threads) ----
    // thread tid<300: o = tid/3 in [0,100) -> (e, half); seg = tid%3 -> d-range
    float2* Pp = AxP;   // reuse (phase-2 reads are fenced off by the LN barriers)
    if (tid < 300) {
        int o = tid / 3, seg = tid - 3 * o;
        int e = o % DEPC, half = o / DEPC;
        const float4* w4 = reinterpret_cast<const float4*>(
            W1w + e * (2 * DD) + half * DD + seg * 100);
        ull acc[4] = {0, 0, 0, 0};
        int dbase = seg * 100;
#pragma unroll 5
        for (int d4 = 0; d4 < 25; d4++) {
            float4 wq = w4[d4];
            int d = dbase + d4 * 4;
            ull w2;
            w2 = pk2(wq.x, wq.x);
#pragma unroll
            for (int rp = 0; rp < 4; rp++) acc[rp] = f2fma(w2, NSU(d + 0, rp), acc[rp]);
            w2 = pk2(wq.y, wq.y);
#pragma unroll
            for (int rp = 0; rp < 4; rp++) acc[rp] = f2fma(w2, NSU(d + 1, rp), acc[rp]);
            w2 = pk2(wq.z, wq.z);
#pragma unroll
            for (int rp = 0; rp < 4; rp++) acc[rp] = f2fma(w2, NSU(d + 2, rp), acc[rp]);
            w2 = pk2(wq.w, wq.w);
#pragma unroll
            for (int rp = 0; rp < 4; rp++) acc[rp] = f2fma(w2, NSU(d + 3, rp), acc[rp]);
        }
#pragma unroll
        for (int rp = 0; rp < 4; rp++)
            Pp[tid * 4 + rp] = *reinterpret_cast<float2*>(&acc[rp]);
    }
    __syncthreads();

    if (tid < 2 * DEPC) {
        int e = tid % DEPC, half = tid / DEPC;
        int o = tid;          // o = half*DEPC + e  == (e,half) index used above
        float pv[RROWS];
#pragma unroll
        for (int rp = 0; rp < 4; rp++) {
            float2 s = make_float2(0.f, 0.f);
#pragma unroll
            for (int seg = 0; seg < 3; seg++) {
                float2 p = Pp[(o * 3 + seg) * 4 + rp];
                s.x += p.x; s.y += p.y;
            }
            pv[2 * rp] = s.x; pv[2 * rp + 1] = s.y;
        }
        float* dst = (half == 0 ? g_Pa : g_Pb) + (b * SS + s0) * DEPC + e;
#pragma unroll
        for (int r = 0; r < RROWS; r++) dst[r * DEPC] = pv[r];
    }
}

// =======================================================================
// Kernel C: edge[b,i,j,e] = pa[b,j,e] + pb[b,i,e] + W1_b[e]
// 26 MB streaming write; float2-vectorized (pairs never straddle e=50).
// =======================================================================
__global__ void k_edge(const float* __restrict__ W1b, float* __restrict__ edge) {
    __shared__ float2 pb2[DEPC / 2];
    const int bi  = blockIdx.x;        // b*S + i
    const int b   = bi >> 7;
    const int tid = threadIdx.x;

    if (tid < DEPC / 2) {
        int e = tid * 2;
        pb2[tid] = make_float2(g_Pb[bi * DEPC + e]     + W1b[e],
                               g_Pb[bi * DEPC + e + 1] + W1b[e + 1]);
    }
    __syncthreads();

    const float2* pa2  = reinterpret_cast<const float2*>(g_Pa + b * SS * DEPC);
    float2*       out2 = reinterpret_cast<float2*>(edge + (size_t)bi * SS * DEPC);
    for (int i2 = tid; i2 < SS * DEPC / 2; i2 += blockDim.x) {
        float2 a = pa2[i2];
        float2 p = pb2[i2 % (DEPC / 2)];
        out2[i2] = make_float2(a.x + p.x, a.y + p.y);
    }
}

// =======================================================================
extern "C" void kernel_launch(void* const* d_in, const int* in_sizes, int n_in,
                              void* d_out, int out_size) {
    const float* wps = (const float*)d_in[0];
    /* d_in[1] = weight_adj (int64) — unused by the reference computation */
    const float* x   = (const float*)d_in[2];
    const float* sl  = (const float*)d_in[3];
    const float* Ww  = (const float*)d_in[4];
    const float* Wb  = (const float*)d_in[5];
    const float* lna = (const float*)d_in[6];
    const float* lnb = (const float*)d_in[7];
    const float* W1w = (const float*)d_in[8];
    const float* W1b = (const float*)d_in[9];

    float* out  = (float*)d_out;
    float* node = out;                       // B*S*D = 307200 floats
    float* edge = out + BB * SS * DD;        // B*S*S*DEP = 6553600 floats

    cudaFuncSetAttribute((const void*)k_fused,
                         cudaFuncAttributeMaxDynamicSharedMemorySize, SMEM_BYTES);

    k_fused<<<BB * (SS / RROWS), NTHR, SMEM_BYTES>>>(wps, sl, x, Ww, Wb, lna, lnb, W1w, node);
    k_edge<<<BB * SS, 256>>>(W1b, edge);
}